// round 15
// baseline (speedup 1.0000x reference)
#include <cuda_runtime.h>

#define BB   256
#define TT   1024
#define SS   7
#define HH   64
#define LL   4
#define OO   3
#define UU   4
#define BETA 0.8f
#define TH   1.0f
#define NEPOCH (TT / UU)      // 256
#define ROWF   68             // padded spike row: half0 at byte 0, half1 at byte 144

// 32-element dot product: spike chunk (16B-aligned) x register weight row.
__device__ __forceinline__ float dot32(const float* __restrict__ sp,
                                       const float* __restrict__ wrow) {
    float a0 = 0.f, a1 = 0.f;
    #pragma unroll
    for (int i = 0; i < 8; i++) {
        float4 sv = *(const float4*)(sp + 4 * i);
        a0 = fmaf(sv.x, wrow[4 * i + 0], a0);
        a1 = fmaf(sv.y, wrow[4 * i + 1], a1);
        a0 = fmaf(sv.z, wrow[4 * i + 2], a0);
        a1 = fmaf(sv.w, wrow[4 * i + 3], a1);
    }
    return a0 + a1;
}

// One CTA per batch element, 512 threads (16 warps), 2 CTAs/SM.
// Warps map to SMSP by wid%4; with exactly 4 warps per layer (l = tid>>7) each
// SMSP gets {layer0-light, layer1, layer2, layer3} -> BALANCED FMA load (the
// R9 17th out-warp put ~132 extra warp-wide FMA/epoch all on SMSP0, which was
// the ~88%-busy bottleneck pipe).
// Unit split as R9: q = tid&127, unit h = q>>1, half = q&1; each thread holds
// half a weight row (32 regs), partial combined via shfl_xor(1); both halves
// run the membrane chain redundantly, half0 stores.
// OUTPUT LAYER: folded into layer-0 warp 0 as 12 pair-tasks (3 outputs x 4
// timesteps), lanes 2p/2p+1 = task p (j=p>>2, k=p&3) -> one warp-wide dot32
// pass (~45 instr) replaces the whole dedicated out warp.
// Pipeline over epochs of UU=4 timesteps, double-buffered spikes, one
// __syncthreads per epoch. Per-timestep math identical to the 352.8us R9.
__global__ __launch_bounds__(512, 2)
void snn_bal_kernel(const float* __restrict__ x,
                    const float* __restrict__ hidden0,
                    const float* __restrict__ w1,
                    const float* __restrict__ b1,
                    const float* __restrict__ w_h,
                    const float* __restrict__ b_h,
                    const float* __restrict__ w_out,
                    const float* __restrict__ b_out,
                    float* __restrict__ out_outputs,   // [B,T,OO]
                    float* __restrict__ out_hidden,    // [B,T,LL,HH]
                    float* __restrict__ out_xcopy)     // [B,T,SS]
{
    const int b    = blockIdx.x;
    const int tid  = threadIdx.x;
    const int lane = tid & 31;

    __shared__ __align__(16) float spk[2][LL][UU][ROWF];

    // ---- copy this batch's x slice to the output buffer (coalesced float4) ----
    {
        const float4* xs4 = (const float4*)(x + (size_t)b * TT * SS);
        float4*       xo4 = (float4*)(out_xcopy + (size_t)b * TT * SS);
        const int n4 = TT * SS / 4;  // 1792
        for (int i = tid; i < n4; i += blockDim.x) xo4[i] = xs4[i];
    }

    const int  l    = tid >> 7;          // layer 0..3
    const int  q    = tid & 127;
    const int  h    = q >> 1;
    const int  half = q & 1;

    // out-duty: warp 0 (lanes 2p,2p+1 = task p; j = p>>2, k = p&3)
    const bool outduty = (tid < 32);
    const int  op = lane >> 1;           // task id 0..15 (12 active)
    const int  oj = op >> 2;             // output index 0..2 (valid for op<12)
    const int  ok = op & 3;              // timestep-in-epoch
    const int  oh = lane & 1;            // half

    float wrow[32];
    float orow[32];
    float w0[4];
    float bias  = 0.0f;
    float obias = 0.0f;
    float m     = 0.0f;
    int   hoff  = 0;

    {
        m    = hidden0[(size_t)b * TT * LL * HH + (size_t)l * HH + h];
        hoff = h + ((h >= 32) ? 4 : 0);
        if (l == 0) {
            bias = b1[h];
            w0[0] = w1[h * SS + half * 4 + 0];
            w0[1] = w1[h * SS + half * 4 + 1];
            w0[2] = w1[h * SS + half * 4 + 2];
            w0[3] = half ? 0.0f : w1[h * SS + 3];
        } else {
            const float* row = w_h + ((size_t)(l - 1) * HH + h) * HH + half * 32;
            #pragma unroll
            for (int i = 0; i < 32; i++) wrow[i] = row[i];
            bias = b_h[(l - 1) * HH + h];
        }
    }
    if (outduty && op < 12) {
        const float* row = w_out + (size_t)oj * HH + oh * 32;
        #pragma unroll
        for (int i = 0; i < 32; i++) orow[i] = row[i];
        obias = b_out[oj];
    }

    __syncthreads();

    const float* xrow   = x + (size_t)b * TT * SS;
    float*       hidptr = out_hidden + (size_t)b * TT * LL * HH + l * HH + h;
    float*       outpB  = out_outputs + (size_t)b * TT * OO;

    int buf = 0;
    for (int e = 0; e < NEPOCH + LL; e++) {
        // ---- layer work (R9-identical) ----
        if (e >= l && e < l + NEPOCH) {
            float p[UU];
            if (l == 0) {
                #pragma unroll
                for (int k = 0; k < UU; k++) {
                    const float* xr = xrow + k * SS + half * 4;
                    float a = 0.f;
                    a = fmaf(xr[0], w0[0], a);
                    a = fmaf(xr[1], w0[1], a);
                    a = fmaf(xr[2], w0[2], a);
                    if (!half) a = fmaf(xr[3], w0[3], a);
                    p[k] = a;
                }
                xrow += UU * SS;
            } else {
                #pragma unroll
                for (int k = 0; k < UU; k++)
                    p[k] = dot32(&spk[buf ^ 1][l - 1][k][half * 36], wrow);
            }
            #pragma unroll
            for (int k = 0; k < UU; k++) {
                const float tot = p[k] + __shfl_xor_sync(0xffffffffu, p[k], 1);
                const float c   = bias + tot;
                const float reset = (m > TH) ? TH : 0.0f;
                const float m_new = fmaf(BETA, m, c) - reset;
                m = m_new;
                if (!half) {
                    spk[buf][l][k][hoff] = (m_new > TH) ? 1.0f : 0.0f;
                    hidptr[(size_t)k * (LL * HH)] = m_new;
                }
            }
            hidptr += (size_t)UU * LL * HH;
        }

        // ---- output duty (warp 0): one warp-wide dot32 pass for all 12 tasks ----
        if (outduty && e >= LL) {
            // spikes of layer 3 written in epoch e-1 -> timesteps (e-1-3)*UU + ok
            float pk  = dot32(&spk[buf ^ 1][LL - 1][ok][oh * 36], orow);
            float tot = pk + __shfl_xor_sync(0xffffffffu, pk, 1);
            if (op < 12 && !oh) {
                const int t = (e - LL) * UU + ok;
                outpB[(size_t)t * OO + oj] = obias + tot;
            }
        }

        __syncthreads();
        buf ^= 1;
    }
}

extern "C" void kernel_launch(void* const* d_in, const int* in_sizes, int n_in,
                              void* d_out, int out_size) {
    // metadata order: x, hidden_states, prev_obs, w1, b1, w_h, b_h, w_out, b_out
    const float* x       = (const float*)d_in[0];
    const float* hidden0 = (const float*)d_in[1];
    // d_in[2] = prev_obs (unused by reference)
    const float* w1      = (const float*)d_in[3];
    const float* b1      = (const float*)d_in[4];
    const float* w_h     = (const float*)d_in[5];
    const float* b_h     = (const float*)d_in[6];
    const float* w_out   = (const float*)d_in[7];
    const float* b_out   = (const float*)d_in[8];

    float* out_outputs = (float*)d_out;                                  // B*T*OO
    float* out_hidden  = out_outputs + (size_t)BB * TT * OO;             // B*T*LL*HH
    float* out_xcopy   = out_hidden + (size_t)BB * TT * LL * HH;         // B*T*SS

    snn_bal_kernel<<<BB, 512>>>(x, hidden0, w1, b1, w_h, b_h, w_out, b_out,
                                out_outputs, out_hidden, out_xcopy);
}

// round 16
// speedup vs baseline: 1.2400x; 1.2400x over previous
#include <cuda_runtime.h>

#define BB   256
#define TT   1024
#define SS   7
#define HH   64
#define LL   4
#define OO   3
#define UU   4
#define BETA 0.8f
#define TH   1.0f
#define NEPOCH (TT / UU)      // 256
#define ROWF   68             // padded spike row: half0 at byte 0, half1 at byte 144

// 32-element dot product: spike chunk (16B-aligned) x register weight row.
__device__ __forceinline__ float dot32(const float* __restrict__ sp,
                                       const float* __restrict__ wrow) {
    float a0 = 0.f, a1 = 0.f;
    #pragma unroll
    for (int i = 0; i < 8; i++) {
        float4 sv = *(const float4*)(sp + 4 * i);
        a0 = fmaf(sv.x, wrow[4 * i + 0], a0);
        a1 = fmaf(sv.y, wrow[4 * i + 1], a1);
        a0 = fmaf(sv.z, wrow[4 * i + 2], a0);
        a1 = fmaf(sv.w, wrow[4 * i + 3], a1);
    }
    return a0 + a1;
}

// One CTA per batch element, 576 threads (18 warps), 2 CTAs/SM.
// tids 0..511: layer threads exactly as the 352.8us R9 kernel:
//   l = tid>>7, q = tid&127, unit h = q>>1, half = q&1. Each thread holds HALF
//   a weight row (32 regs), partial combined via shfl_xor(1); both halves run
//   the membrane chain redundantly, half0 stores spikes/hidden.
// Warps 16,17: OUTPUT layer, restructured from R9's single warp (which did 4
//   sequential warp-wide dot passes, all costed on SMSP0) into two warps doing
//   ONE warp-wide dot pass each over 6 pair-tasks (task p = (j=p>>2, k=p&3);
//   lanes 2q/2q+1 = halves). This (a) cuts out-layer instructions ~4x and
//   (b) spreads them over SMSP0+SMSP1, lowering the max per-SMSP FMA load.
// Same wrow register array reused for out weights -> regs stay 56
// (1152 thr x 56 = 64512 <= 64K, 2 CTAs/SM preserved).
// Pipeline over epochs of UU=4 timesteps, double-buffered spikes, one
// __syncthreads per epoch. Per-timestep math identical to R9.
__global__ __launch_bounds__(576, 2)
void snn_bal2_kernel(const float* __restrict__ x,
                     const float* __restrict__ hidden0,
                     const float* __restrict__ w1,
                     const float* __restrict__ b1,
                     const float* __restrict__ w_h,
                     const float* __restrict__ b_h,
                     const float* __restrict__ w_out,
                     const float* __restrict__ b_out,
                     float* __restrict__ out_outputs,   // [B,T,OO]
                     float* __restrict__ out_hidden,    // [B,T,LL,HH]
                     float* __restrict__ out_xcopy)     // [B,T,SS]
{
    const int b    = blockIdx.x;
    const int tid  = threadIdx.x;
    const int lane = tid & 31;

    __shared__ __align__(16) float spk[2][LL][UU][ROWF];

    // ---- copy this batch's x slice to the output buffer (coalesced float4) ----
    {
        const float4* xs4 = (const float4*)(x + (size_t)b * TT * SS);
        float4*       xo4 = (float4*)(out_xcopy + (size_t)b * TT * SS);
        const int n4 = TT * SS / 4;  // 1792
        for (int i = tid; i < n4; i += blockDim.x) xo4[i] = xs4[i];
    }

    const bool is_layer = (tid < LL * HH * 2);           // 512
    const int  l    = tid >> 7;
    const int  q    = tid & 127;
    const int  h    = q >> 1;
    const int  half = q & 1;

    // out warps: warp 16 -> tasks 0..5, warp 17 -> tasks 6..11
    const int  wid   = tid >> 5;
    const bool is_out = (wid >= 16);
    const int  opraw  = (wid - 16) * 6 + (lane >> 1);    // task id (clamped below)
    const int  op     = (opraw < 12) ? opraw : 11;
    const int  oactive = is_out && (opraw < 12);
    const int  oj = op >> 2;            // output index 0..2
    const int  ok = op & 3;             // timestep-in-epoch 0..3
    const int  oh = lane & 1;           // half

    float wrow[32];
    float w0[4];
    float bias = 0.0f;
    float m    = 0.0f;
    int   hoff = 0;

    if (is_layer) {
        m    = hidden0[(size_t)b * TT * LL * HH + (size_t)l * HH + h];
        hoff = h + ((h >= 32) ? 4 : 0);
        if (l == 0) {
            bias = b1[h];
            w0[0] = w1[h * SS + half * 4 + 0];
            w0[1] = w1[h * SS + half * 4 + 1];
            w0[2] = w1[h * SS + half * 4 + 2];
            w0[3] = half ? 0.0f : w1[h * SS + 3];
        } else {
            const float* row = w_h + ((size_t)(l - 1) * HH + h) * HH + half * 32;
            #pragma unroll
            for (int i = 0; i < 32; i++) wrow[i] = row[i];
            bias = b_h[(l - 1) * HH + h];
        }
    } else {
        const float* row = w_out + (size_t)oj * HH + oh * 32;
        #pragma unroll
        for (int i = 0; i < 32; i++) wrow[i] = row[i];
        bias = b_out[oj];
    }

    __syncthreads();

    const float* xrow   = x + (size_t)b * TT * SS;
    float*       hidptr = out_hidden + (size_t)b * TT * LL * HH
                          + (is_layer ? (l * HH + h) : 0);
    float*       outptr = out_outputs + (size_t)b * TT * OO + (is_out ? (ok * OO + oj) : 0);

    int buf = 0;
    for (int e = 0; e < NEPOCH + LL; e++) {
        if (is_layer) {
            if (e >= l && e < l + NEPOCH) {
                float p[UU];
                if (l == 0) {
                    #pragma unroll
                    for (int k = 0; k < UU; k++) {
                        const float* xr = xrow + k * SS + half * 4;
                        float a = 0.f;
                        a = fmaf(xr[0], w0[0], a);
                        a = fmaf(xr[1], w0[1], a);
                        a = fmaf(xr[2], w0[2], a);
                        if (!half) a = fmaf(xr[3], w0[3], a);
                        p[k] = a;
                    }
                    xrow += UU * SS;
                } else {
                    #pragma unroll
                    for (int k = 0; k < UU; k++)
                        p[k] = dot32(&spk[buf ^ 1][l - 1][k][half * 36], wrow);
                }
                #pragma unroll
                for (int k = 0; k < UU; k++) {
                    const float tot = p[k] + __shfl_xor_sync(0xffffffffu, p[k], 1);
                    const float c   = bias + tot;
                    const float reset = (m > TH) ? TH : 0.0f;
                    const float m_new = fmaf(BETA, m, c) - reset;
                    m = m_new;
                    if (!half) {
                        spk[buf][l][k][hoff] = (m_new > TH) ? 1.0f : 0.0f;
                        hidptr[(size_t)k * (LL * HH)] = m_new;
                    }
                }
                hidptr += (size_t)UU * LL * HH;
            }
        } else {
            if (e >= LL) {
                // one warp-wide dot pass serves all this warp's 6 pair-tasks
                float pk  = dot32(&spk[buf ^ 1][LL - 1][ok][oh * 36], wrow);
                float tot = pk + __shfl_xor_sync(0xffffffffu, pk, 1);
                if (oactive && !oh) *outptr = bias + tot;
                outptr += UU * OO;
            }
        }
        __syncthreads();
        buf ^= 1;
    }
}

extern "C" void kernel_launch(void* const* d_in, const int* in_sizes, int n_in,
                              void* d_out, int out_size) {
    // metadata order: x, hidden_states, prev_obs, w1, b1, w_h, b_h, w_out, b_out
    const float* x       = (const float*)d_in[0];
    const float* hidden0 = (const float*)d_in[1];
    // d_in[2] = prev_obs (unused by reference)
    const float* w1      = (const float*)d_in[3];
    const float* b1      = (const float*)d_in[4];
    const float* w_h     = (const float*)d_in[5];
    const float* b_h     = (const float*)d_in[6];
    const float* w_out   = (const float*)d_in[7];
    const float* b_out   = (const float*)d_in[8];

    float* out_outputs = (float*)d_out;                                  // B*T*OO
    float* out_hidden  = out_outputs + (size_t)BB * TT * OO;             // B*T*LL*HH
    float* out_xcopy   = out_hidden + (size_t)BB * TT * LL * HH;         // B*T*SS

    snn_bal2_kernel<<<BB, 576>>>(x, hidden0, w1, b1, w_h, b_h, w_out, b_out,
                                 out_outputs, out_hidden, out_xcopy);
}